// round 3
// baseline (speedup 1.0000x reference)
#include <cuda_runtime.h>
#include <cuda_bf16.h>
#include <math.h>
#include <stdint.h>

#define NQ 8192
#define DQ 128
#define EQ 262144
#define EDIM 50
#define HID 32

// ---------------- scratch (device globals: no allocation allowed) ----------------
__device__ float          g_scores [(size_t)NQ * NQ];    // 256 MiB fp32 logits
__device__ __nv_bfloat16  g_attn_hi[(size_t)NQ * NQ];    // 128 MiB
__device__ __nv_bfloat16  g_attn_lo[(size_t)NQ * NQ];    // 128 MiB
__device__ __nv_bfloat16  g_ab_hi  [(size_t)NQ * 256];   // [N][a|b], K=256
__device__ __nv_bfloat16  g_ab_lo  [(size_t)NQ * 256];
__device__ __nv_bfloat16  g_mpT_hi [(size_t)256 * NQ];   // [mag|phase]^T
__device__ __nv_bfloat16  g_mpT_lo [(size_t)256 * NQ];

__device__ __forceinline__ void split_bf16(float x, __nv_bfloat16& hi, __nv_bfloat16& lo) {
    hi = __float2bfloat16(x);
    lo = __float2bfloat16(x - __bfloat162float(hi));
}

// ---------------- K1: prep a,b (hi/lo) and transposed mag/phase (hi/lo) ----------------
__global__ void prep_kernel(const float* __restrict__ mag, const float* __restrict__ phase) {
    int idx = blockIdx.x * blockDim.x + threadIdx.x;   // < N*D
    int i = idx >> 7;
    int d = idx & 127;
    float m = mag[idx];
    float p = phase[idx];
    float s, c;
    __sincosf(p, &s, &c);
    __nv_bfloat16 h, l;
    split_bf16(m * c, h, l);
    g_ab_hi[(size_t)i * 256 + d] = h;  g_ab_lo[(size_t)i * 256 + d] = l;
    split_bf16(m * s, h, l);
    g_ab_hi[(size_t)i * 256 + 128 + d] = h;  g_ab_lo[(size_t)i * 256 + 128 + d] = l;
    split_bf16(m, h, l);
    g_mpT_hi[(size_t)d * NQ + i] = h;  g_mpT_lo[(size_t)d * NQ + i] = l;
    split_bf16(p, h, l);
    g_mpT_hi[(size_t)(128 + d) * NQ + i] = h;  g_mpT_lo[(size_t)(128 + d) * NQ + i] = l;
}

// ---------------- GEMM: C[M,N] = (Ahi+Alo)[M,K] * (Bhi+Blo)[N,K]^T, 3-term bf16 split ----
// BM=BN=128, BK=32, 256 threads, 8 warps 2x4, warp tile 64x32, mma m16n8k16
// MODE 0: A=B=g_ab (K=256), C=g_scores, scaled by 1/sqrt(D)
// MODE 1: A=g_attn, B=g_mpT (K=8192, split-K over blockIdx.z), atomicAdd into Cout
template <int MODE>
__global__ __launch_bounds__(256)
void gemm_kernel(float* __restrict__ Cout, float scale) {
    __shared__ __align__(16) __nv_bfloat16 sAh[128][40];
    __shared__ __align__(16) __nv_bfloat16 sAl[128][40];
    __shared__ __align__(16) __nv_bfloat16 sBh[128][40];
    __shared__ __align__(16) __nv_bfloat16 sBl[128][40];

    const int K = (MODE == 0) ? 256 : NQ;
    const __nv_bfloat16* Ahi = (MODE == 0) ? g_ab_hi : g_attn_hi;
    const __nv_bfloat16* Alo = (MODE == 0) ? g_ab_lo : g_attn_lo;
    const __nv_bfloat16* Bhi = (MODE == 0) ? g_ab_hi : g_mpT_hi;
    const __nv_bfloat16* Blo = (MODE == 0) ? g_ab_lo : g_mpT_lo;

    int tid = threadIdx.x;
    int bm = blockIdx.y, bn = blockIdx.x;
    int warp = tid >> 5, lane = tid & 31;
    int wm = warp >> 2, wn = warp & 3;
    int g = lane >> 2, q = lane & 3;

    float acc[4][4][4];
#pragma unroll
    for (int mi = 0; mi < 4; mi++)
#pragma unroll
        for (int ni = 0; ni < 4; ni++)
#pragma unroll
            for (int r = 0; r < 4; r++) acc[mi][ni][r] = 0.f;

    const __nv_bfloat16* Abh = Ahi + (size_t)bm * 128 * K;
    const __nv_bfloat16* Abl = Alo + (size_t)bm * 128 * K;
    const __nv_bfloat16* Bbh = Bhi + (size_t)bn * 128 * K;
    const __nv_bfloat16* Bbl = Blo + (size_t)bn * 128 * K;

    int kbeg = (MODE == 0) ? 0 : blockIdx.z * (NQ / 4);
    int kend = (MODE == 0) ? 256 : kbeg + (NQ / 4);

    int lr = tid >> 2;        // 0..63
    int lc = (tid & 3) * 8;   // bf16 col of uint4

    for (int k0 = kbeg; k0 < kend; k0 += 32) {
#pragma unroll
        for (int it = 0; it < 2; it++) {
            int r = lr + it * 64;
            size_t go = (size_t)r * K + k0 + lc;
            *(uint4*)&sAh[r][lc] = *(const uint4*)(Abh + go);
            *(uint4*)&sAl[r][lc] = *(const uint4*)(Abl + go);
            *(uint4*)&sBh[r][lc] = *(const uint4*)(Bbh + go);
            *(uint4*)&sBl[r][lc] = *(const uint4*)(Bbl + go);
        }
        __syncthreads();

#pragma unroll
        for (int kk = 0; kk < 2; kk++) {
            unsigned rah[4][4], ral[4][4], rbh[4][2], rbl[4][2];
            int c0 = kk * 16 + 2 * q;
#pragma unroll
            for (int mi = 0; mi < 4; mi++) {
                int r0 = wm * 64 + mi * 16 + g;
                rah[mi][0] = *(const unsigned*)&sAh[r0][c0];
                rah[mi][1] = *(const unsigned*)&sAh[r0 + 8][c0];
                rah[mi][2] = *(const unsigned*)&sAh[r0][c0 + 8];
                rah[mi][3] = *(const unsigned*)&sAh[r0 + 8][c0 + 8];
                ral[mi][0] = *(const unsigned*)&sAl[r0][c0];
                ral[mi][1] = *(const unsigned*)&sAl[r0 + 8][c0];
                ral[mi][2] = *(const unsigned*)&sAl[r0][c0 + 8];
                ral[mi][3] = *(const unsigned*)&sAl[r0 + 8][c0 + 8];
            }
#pragma unroll
            for (int ni = 0; ni < 4; ni++) {
                int r0 = wn * 32 + ni * 8 + g;
                rbh[ni][0] = *(const unsigned*)&sBh[r0][c0];
                rbh[ni][1] = *(const unsigned*)&sBh[r0][c0 + 8];
                rbl[ni][0] = *(const unsigned*)&sBl[r0][c0];
                rbl[ni][1] = *(const unsigned*)&sBl[r0][c0 + 8];
            }
#define MMA(AA, BB)                                                                \
    asm volatile(                                                                  \
        "mma.sync.aligned.m16n8k16.row.col.f32.bf16.bf16.f32 "                     \
        "{%0,%1,%2,%3}, {%4,%5,%6,%7}, {%8,%9}, {%0,%1,%2,%3};\n"                  \
        : "+f"(acc[mi][ni][0]), "+f"(acc[mi][ni][1]),                              \
          "+f"(acc[mi][ni][2]), "+f"(acc[mi][ni][3])                               \
        : "r"(AA[mi][0]), "r"(AA[mi][1]), "r"(AA[mi][2]), "r"(AA[mi][3]),          \
          "r"(BB[ni][0]), "r"(BB[ni][1]))
#pragma unroll
            for (int mi = 0; mi < 4; mi++)
#pragma unroll
                for (int ni = 0; ni < 4; ni++) {
                    MMA(rah, rbh);
                    MMA(rah, rbl);
                    MMA(ral, rbh);
                }
#undef MMA
        }
        __syncthreads();
    }

    // epilogue
#pragma unroll
    for (int mi = 0; mi < 4; mi++) {
        int r0 = bm * 128 + wm * 64 + mi * 16 + g;
#pragma unroll
        for (int ni = 0; ni < 4; ni++) {
            int c0 = bn * 128 + wn * 32 + ni * 8 + 2 * q;
            if (MODE == 0) {
                *(float2*)&g_scores[(size_t)r0 * NQ + c0] =
                    make_float2(acc[mi][ni][0] * scale, acc[mi][ni][1] * scale);
                *(float2*)&g_scores[(size_t)(r0 + 8) * NQ + c0] =
                    make_float2(acc[mi][ni][2] * scale, acc[mi][ni][3] * scale);
            } else {
                // cols [0,128) -> new_mag block, [128,256) -> new_phase block
                size_t base = (c0 < 128) ? 0 : ((size_t)NQ * 128 - 128);
                atomicAdd(&Cout[base + (size_t)r0 * 128 + c0], acc[mi][ni][0]);
                atomicAdd(&Cout[base + (size_t)r0 * 128 + c0 + 1], acc[mi][ni][1]);
                atomicAdd(&Cout[base + (size_t)(r0 + 8) * 128 + c0], acc[mi][ni][2]);
                atomicAdd(&Cout[base + (size_t)(r0 + 8) * 128 + c0 + 1], acc[mi][ni][3]);
            }
        }
    }
}

// ---------------- K3: edge bias MLP + scatter-add onto scores (edge_index is int32) ----
__global__ void bias_kernel(const int* __restrict__ ei, const float* __restrict__ rbf,
                            const float* __restrict__ W1, const float* __restrict__ b1,
                            const float* __restrict__ W2, const float* __restrict__ b2) {
    __shared__ float sW1[EDIM * HID];
    __shared__ float sb1[HID], sW2[HID];
    __shared__ float sb2;
    for (int t = threadIdx.x; t < EDIM * HID; t += blockDim.x) sW1[t] = W1[t];
    if (threadIdx.x < HID) { sb1[threadIdx.x] = b1[threadIdx.x]; sW2[threadIdx.x] = W2[threadIdx.x]; }
    if (threadIdx.x == 0) sb2 = b2[0];
    __syncthreads();

    int e = blockIdx.x * blockDim.x + threadIdx.x;
    if (e >= EQ) return;

    float h[HID];
#pragma unroll
    for (int j = 0; j < HID; j++) h[j] = sb1[j];
    const float* r = rbf + (size_t)e * EDIM;
    for (int k = 0; k < EDIM; k++) {
        float rv = __ldg(&r[k]);
#pragma unroll
        for (int j = 0; j < HID; j++) h[j] = fmaf(rv, sW1[k * HID + j], h[j]);
    }
    float bias = sb2;
#pragma unroll
    for (int j = 0; j < HID; j++) {
        float x = h[j];
        float si = x / (1.f + __expf(-x));   // SiLU
        bias = fmaf(si, sW2[j], bias);
    }
    int i  = ei[e];
    int jn = ei[EQ + e];
    atomicAdd(&g_scores[(size_t)i * NQ + jn], bias);
}

// ---------------- K4: row softmax fp32, emit attn as bf16 hi/lo pair ----------------
__global__ __launch_bounds__(256)
void softmax_kernel() {
    __shared__ __align__(16) float4 srow[NQ / 4];   // 32 KB: whole row resident
    __shared__ float red[8];
    int row = blockIdx.x, tid = threadIdx.x;
    const float4* src = (const float4*)(g_scores + (size_t)row * NQ);

    float m = -1e30f;
    for (int u = tid; u < NQ / 4; u += 256) {
        float4 v = src[u];
        srow[u] = v;
        m = fmaxf(m, fmaxf(fmaxf(v.x, v.y), fmaxf(v.z, v.w)));
    }
#pragma unroll
    for (int o = 16; o; o >>= 1) m = fmaxf(m, __shfl_xor_sync(0xffffffffu, m, o));
    if ((tid & 31) == 0) red[tid >> 5] = m;
    __syncthreads();
    float bm = red[0];
#pragma unroll
    for (int w = 1; w < 8; w++) bm = fmaxf(bm, red[w]);
    __syncthreads();

    float sum = 0.f;
    for (int u = tid; u < NQ / 4; u += 256) {
        float4 v = srow[u];
        v.x = __expf(v.x - bm); v.y = __expf(v.y - bm);
        v.z = __expf(v.z - bm); v.w = __expf(v.w - bm);
        srow[u] = v;
        sum += v.x + v.y + v.z + v.w;
    }
#pragma unroll
    for (int o = 16; o; o >>= 1) sum += __shfl_xor_sync(0xffffffffu, sum, o);
    if ((tid & 31) == 0) red[tid >> 5] = sum;
    __syncthreads();
    float tot = 0.f;
#pragma unroll
    for (int w = 0; w < 8; w++) tot += red[w];
    float inv = 1.f / tot;

    uint2* dhi = (uint2*)(g_attn_hi + (size_t)row * NQ);
    uint2* dlo = (uint2*)(g_attn_lo + (size_t)row * NQ);
    for (int u = tid; u < NQ / 4; u += 256) {
        float4 v = srow[u];
        float p0 = v.x * inv, p1 = v.y * inv, p2 = v.z * inv, p3 = v.w * inv;
        __nv_bfloat16 h0, l0, h1, l1, h2, l2, h3, l3;
        split_bf16(p0, h0, l0); split_bf16(p1, h1, l1);
        split_bf16(p2, h2, l2); split_bf16(p3, h3, l3);
        __nv_bfloat162 hp0 = {h0, h1}, hp1 = {h2, h3};
        __nv_bfloat162 lp0 = {l0, l1}, lp1 = {l2, l3};
        uint2 oh, ol;
        oh.x = *(unsigned*)&hp0; oh.y = *(unsigned*)&hp1;
        ol.x = *(unsigned*)&lp0; ol.y = *(unsigned*)&lp1;
        dhi[u] = oh;
        dlo[u] = ol;
    }
}

// ---------------- K5: zero output (required before atomic split-K epilogue) ----------
__global__ void zero_kernel(float* __restrict__ out) {
    out[(size_t)blockIdx.x * 256 + threadIdx.x] = 0.f;
}

// ---------------- launch ----------------
extern "C" void kernel_launch(void* const* d_in, const int* in_sizes, int n_in,
                              void* d_out, int out_size) {
    const float* mag   = (const float*)d_in[0];
    const float* phase = (const float*)d_in[1];
    const int*   ei    = (const int*)d_in[2];
    const float* rbf   = (const float*)d_in[3];
    const float* W1    = (const float*)d_in[4];
    const float* b1    = (const float*)d_in[5];
    const float* W2    = (const float*)d_in[6];
    const float* b2    = (const float*)d_in[7];
    float*       out   = (float*)d_out;

    const float inv_sqrt_d = 0.08838834764831843f;   // 1/sqrt(128)

    prep_kernel<<<(NQ * DQ) / 256, 256>>>(mag, phase);
    gemm_kernel<0><<<dim3(NQ / 128, NQ / 128), 256>>>(nullptr, inv_sqrt_d);
    bias_kernel<<<EQ / 256, 256>>>(ei, rbf, W1, b1, W2, b2);
    softmax_kernel<<<NQ, 256>>>();
    zero_kernel<<<(NQ * 256) / 256, 256>>>(out);
    gemm_kernel<1><<<dim3(2, NQ / 128, 4), 256>>>(out, 1.0f);
}

// round 4
// speedup vs baseline: 1.4693x; 1.4693x over previous
#include <cuda_runtime.h>
#include <cuda_bf16.h>
#include <math.h>
#include <stdint.h>

#define NQ 8192
#define DQ 128
#define EQ 262144
#define EDIM 50
#define HID 32

// ---------------- scratch (device globals: no allocation allowed) ----------------
__device__ float          g_scores [(size_t)NQ * NQ];    // 256 MiB fp32 logits
__device__ __nv_bfloat16  g_attn_hi[(size_t)NQ * NQ];    // 128 MiB
__device__ __nv_bfloat16  g_attn_lo[(size_t)NQ * NQ];    // 128 MiB
__device__ __nv_bfloat16  g_ab_hi  [(size_t)NQ * 256];   // [N][a|b], K=256
__device__ __nv_bfloat16  g_ab_lo  [(size_t)NQ * 256];
__device__ __nv_bfloat16  g_mpT_hi [(size_t)256 * NQ];   // [mag|phase]^T
__device__ __nv_bfloat16  g_mpT_lo [(size_t)256 * NQ];

__device__ __forceinline__ void split_bf16(float x, __nv_bfloat16& hi, __nv_bfloat16& lo) {
    hi = __float2bfloat16(x);
    lo = __float2bfloat16(x - __bfloat162float(hi));
}

__device__ __forceinline__ void cp_async16(void* sdst, const void* gsrc) {
    unsigned s = (unsigned)__cvta_generic_to_shared(sdst);
    asm volatile("cp.async.cg.shared.global [%0], [%1], 16;\n" :: "r"(s), "l"(gsrc));
}
#define CP_COMMIT() asm volatile("cp.async.commit_group;\n" ::: "memory")
#define CP_WAIT1()  asm volatile("cp.async.wait_group 1;\n" ::: "memory")

// ---------------- K1: prep a,b (hi/lo) and transposed mag/phase (hi/lo) ----------------
__global__ void prep_kernel(const float* __restrict__ mag, const float* __restrict__ phase) {
    int idx = blockIdx.x * blockDim.x + threadIdx.x;   // < N*D
    int i = idx >> 7;
    int d = idx & 127;
    float m = mag[idx];
    float p = phase[idx];
    float s, c;
    __sincosf(p, &s, &c);
    __nv_bfloat16 h, l;
    split_bf16(m * c, h, l);
    g_ab_hi[(size_t)i * 256 + d] = h;  g_ab_lo[(size_t)i * 256 + d] = l;
    split_bf16(m * s, h, l);
    g_ab_hi[(size_t)i * 256 + 128 + d] = h;  g_ab_lo[(size_t)i * 256 + 128 + d] = l;
    split_bf16(m, h, l);
    g_mpT_hi[(size_t)d * NQ + i] = h;  g_mpT_lo[(size_t)d * NQ + i] = l;
    split_bf16(p, h, l);
    g_mpT_hi[(size_t)(128 + d) * NQ + i] = h;  g_mpT_lo[(size_t)(128 + d) * NQ + i] = l;
}

// ---------------- GEMM: C[M,N] = (Ahi+Alo)[M,K] * (Bhi+Blo)[N,K]^T, 3-term bf16 split ----
// BM=BN=128, BK=32, 256 threads, 8 warps 2x4, warp tile 64x32, mma m16n8k16
// cp.async 2-stage double buffer; dynamic smem 80 KB.
// MODE 0: A=B=g_ab (K=256), C=g_scores, scaled; SYMMETRIC: only bm<=bn tiles run,
//         each off-diagonal tile also writes its transpose.
// MODE 1: A=g_attn, B=g_mpT (K=8192, split-K over blockIdx.z), atomicAdd into Cout
#define TSTRIDE 40
#define TSZ (128 * TSTRIDE)

template <int MODE>
__global__ __launch_bounds__(256)
void gemm_kernel(float* __restrict__ Cout, float scale) {
    extern __shared__ __align__(16) __nv_bfloat16 dsm[];   // [2 stages][4 tensors][128][40]

    const int bm = blockIdx.y, bn = blockIdx.x;
    if (MODE == 0 && bn < bm) return;   // symmetric: upper-triangle tiles only

    const int K = (MODE == 0) ? 256 : NQ;
    const __nv_bfloat16* Ahi = (MODE == 0) ? g_ab_hi : g_attn_hi;
    const __nv_bfloat16* Alo = (MODE == 0) ? g_ab_lo : g_attn_lo;
    const __nv_bfloat16* Bhi = (MODE == 0) ? g_ab_hi : g_mpT_hi;
    const __nv_bfloat16* Blo = (MODE == 0) ? g_ab_lo : g_mpT_lo;

    const int tid = threadIdx.x;
    const int warp = tid >> 5, lane = tid & 31;
    const int wm = warp >> 2, wn = warp & 3;
    const int g = lane >> 2, q = lane & 3;

    float acc[4][4][4];
#pragma unroll
    for (int mi = 0; mi < 4; mi++)
#pragma unroll
        for (int ni = 0; ni < 4; ni++)
#pragma unroll
            for (int r = 0; r < 4; r++) acc[mi][ni][r] = 0.f;

    const __nv_bfloat16* Abh = Ahi + (size_t)bm * 128 * K;
    const __nv_bfloat16* Abl = Alo + (size_t)bm * 128 * K;
    const __nv_bfloat16* Bbh = Bhi + (size_t)bn * 128 * K;
    const __nv_bfloat16* Bbl = Blo + (size_t)bn * 128 * K;

    const int kbeg = (MODE == 0) ? 0 : blockIdx.z * (NQ / 4);
    const int nit = ((MODE == 0) ? 256 : NQ / 4) / 32;

    const int lr = tid >> 2;        // 0..63
    const int lc = (tid & 3) * 8;   // bf16 col of uint4

    // prefetch helper (macro to keep everything in-registers)
#define PREFETCH(IT, ST)                                                         \
    do {                                                                         \
        int k0_ = kbeg + (IT) * 32;                                              \
        __nv_bfloat16* d_ = dsm + (ST) * 4 * TSZ;                                \
        _Pragma("unroll")                                                        \
        for (int hf = 0; hf < 2; hf++) {                                         \
            int r_ = lr + hf * 64;                                               \
            size_t go_ = (size_t)r_ * K + k0_ + lc;                              \
            int so_ = r_ * TSTRIDE + lc;                                         \
            cp_async16(d_ + 0 * TSZ + so_, Abh + go_);                           \
            cp_async16(d_ + 1 * TSZ + so_, Abl + go_);                           \
            cp_async16(d_ + 2 * TSZ + so_, Bbh + go_);                           \
            cp_async16(d_ + 3 * TSZ + so_, Bbl + go_);                           \
        }                                                                        \
    } while (0)

    PREFETCH(0, 0);
    CP_COMMIT();

    for (int it = 0; it < nit; it++) {
        if (it + 1 < nit) PREFETCH(it + 1, (it + 1) & 1);
        CP_COMMIT();
        CP_WAIT1();
        __syncthreads();

        const __nv_bfloat16* sAh = dsm + (it & 1) * 4 * TSZ + 0 * TSZ;
        const __nv_bfloat16* sAl = dsm + (it & 1) * 4 * TSZ + 1 * TSZ;
        const __nv_bfloat16* sBh = dsm + (it & 1) * 4 * TSZ + 2 * TSZ;
        const __nv_bfloat16* sBl = dsm + (it & 1) * 4 * TSZ + 3 * TSZ;

#pragma unroll
        for (int kk = 0; kk < 2; kk++) {
            unsigned rah[4][4], ral[4][4], rbh[4][2], rbl[4][2];
            int c0 = kk * 16 + 2 * q;
#pragma unroll
            for (int mi = 0; mi < 4; mi++) {
                int r0 = (wm * 64 + mi * 16 + g) * TSTRIDE;
                rah[mi][0] = *(const unsigned*)&sAh[r0 + c0];
                rah[mi][1] = *(const unsigned*)&sAh[r0 + 8 * TSTRIDE + c0];
                rah[mi][2] = *(const unsigned*)&sAh[r0 + c0 + 8];
                rah[mi][3] = *(const unsigned*)&sAh[r0 + 8 * TSTRIDE + c0 + 8];
                ral[mi][0] = *(const unsigned*)&sAl[r0 + c0];
                ral[mi][1] = *(const unsigned*)&sAl[r0 + 8 * TSTRIDE + c0];
                ral[mi][2] = *(const unsigned*)&sAl[r0 + c0 + 8];
                ral[mi][3] = *(const unsigned*)&sAl[r0 + 8 * TSTRIDE + c0 + 8];
            }
#pragma unroll
            for (int ni = 0; ni < 4; ni++) {
                int r0 = (wn * 32 + ni * 8 + g) * TSTRIDE;
                rbh[ni][0] = *(const unsigned*)&sBh[r0 + c0];
                rbh[ni][1] = *(const unsigned*)&sBh[r0 + c0 + 8];
                rbl[ni][0] = *(const unsigned*)&sBl[r0 + c0];
                rbl[ni][1] = *(const unsigned*)&sBl[r0 + c0 + 8];
            }
#define MMA(AA, BB)                                                                \
    asm volatile(                                                                  \
        "mma.sync.aligned.m16n8k16.row.col.f32.bf16.bf16.f32 "                     \
        "{%0,%1,%2,%3}, {%4,%5,%6,%7}, {%8,%9}, {%0,%1,%2,%3};\n"                  \
        : "+f"(acc[mi][ni][0]), "+f"(acc[mi][ni][1]),                              \
          "+f"(acc[mi][ni][2]), "+f"(acc[mi][ni][3])                               \
        : "r"(AA[mi][0]), "r"(AA[mi][1]), "r"(AA[mi][2]), "r"(AA[mi][3]),          \
          "r"(BB[ni][0]), "r"(BB[ni][1]))
#pragma unroll
            for (int mi = 0; mi < 4; mi++)
#pragma unroll
                for (int ni = 0; ni < 4; ni++) {
                    MMA(rah, rbh);
                    MMA(rah, rbl);
                    MMA(ral, rbh);
                }
#undef MMA
        }
        __syncthreads();
    }
#undef PREFETCH

    // epilogue
#pragma unroll
    for (int mi = 0; mi < 4; mi++) {
        int r0 = bm * 128 + wm * 64 + mi * 16 + g;
#pragma unroll
        for (int ni = 0; ni < 4; ni++) {
            int c0 = bn * 128 + wn * 32 + ni * 8 + 2 * q;
            if (MODE == 0) {
                float v0 = acc[mi][ni][0] * scale, v1 = acc[mi][ni][1] * scale;
                float v2 = acc[mi][ni][2] * scale, v3 = acc[mi][ni][3] * scale;
                *(float2*)&g_scores[(size_t)r0 * NQ + c0]       = make_float2(v0, v1);
                *(float2*)&g_scores[(size_t)(r0 + 8) * NQ + c0] = make_float2(v2, v3);
                if (bm != bn) {   // symmetric mirror
                    g_scores[(size_t)c0 * NQ + r0]           = v0;
                    g_scores[(size_t)(c0 + 1) * NQ + r0]     = v1;
                    g_scores[(size_t)c0 * NQ + r0 + 8]       = v2;
                    g_scores[(size_t)(c0 + 1) * NQ + r0 + 8] = v3;
                }
            } else {
                // cols [0,128) -> new_mag block, [128,256) -> new_phase block
                size_t base = (c0 < 128) ? 0 : ((size_t)NQ * 128 - 128);
                atomicAdd(&Cout[base + (size_t)r0 * 128 + c0], acc[mi][ni][0]);
                atomicAdd(&Cout[base + (size_t)r0 * 128 + c0 + 1], acc[mi][ni][1]);
                atomicAdd(&Cout[base + (size_t)(r0 + 8) * 128 + c0], acc[mi][ni][2]);
                atomicAdd(&Cout[base + (size_t)(r0 + 8) * 128 + c0 + 1], acc[mi][ni][3]);
            }
        }
    }
}

// ---------------- K3: edge bias MLP + scatter-add onto scores (edge_index is int32) ----
__global__ void bias_kernel(const int* __restrict__ ei, const float* __restrict__ rbf,
                            const float* __restrict__ W1, const float* __restrict__ b1,
                            const float* __restrict__ W2, const float* __restrict__ b2) {
    __shared__ float sW1[EDIM * HID];
    __shared__ float sb1[HID], sW2[HID];
    __shared__ float sb2;
    for (int t = threadIdx.x; t < EDIM * HID; t += blockDim.x) sW1[t] = W1[t];
    if (threadIdx.x < HID) { sb1[threadIdx.x] = b1[threadIdx.x]; sW2[threadIdx.x] = W2[threadIdx.x]; }
    if (threadIdx.x == 0) sb2 = b2[0];
    __syncthreads();

    int e = blockIdx.x * blockDim.x + threadIdx.x;
    if (e >= EQ) return;

    float h[HID];
#pragma unroll
    for (int j = 0; j < HID; j++) h[j] = sb1[j];
    const float* r = rbf + (size_t)e * EDIM;
    for (int k = 0; k < EDIM; k++) {
        float rv = __ldg(&r[k]);
#pragma unroll
        for (int j = 0; j < HID; j++) h[j] = fmaf(rv, sW1[k * HID + j], h[j]);
    }
    float bias = sb2;
#pragma unroll
    for (int j = 0; j < HID; j++) {
        float x = h[j];
        float si = x / (1.f + __expf(-x));   // SiLU
        bias = fmaf(si, sW2[j], bias);
    }
    int i  = ei[e];
    int jn = ei[EQ + e];
    atomicAdd(&g_scores[(size_t)i * NQ + jn], bias);
}

// ---------------- K4: row softmax fp32, emit attn as bf16 hi/lo pair ----------------
__global__ __launch_bounds__(256)
void softmax_kernel() {
    __shared__ __align__(16) float4 srow[NQ / 4];   // 32 KB: whole row resident
    __shared__ float red[8];
    int row = blockIdx.x, tid = threadIdx.x;
    const float4* src = (const float4*)(g_scores + (size_t)row * NQ);

    float m = -1e30f;
    for (int u = tid; u < NQ / 4; u += 256) {
        float4 v = src[u];
        srow[u] = v;
        m = fmaxf(m, fmaxf(fmaxf(v.x, v.y), fmaxf(v.z, v.w)));
    }
#pragma unroll
    for (int o = 16; o; o >>= 1) m = fmaxf(m, __shfl_xor_sync(0xffffffffu, m, o));
    if ((tid & 31) == 0) red[tid >> 5] = m;
    __syncthreads();
    float bm = red[0];
#pragma unroll
    for (int w = 1; w < 8; w++) bm = fmaxf(bm, red[w]);
    __syncthreads();

    float sum = 0.f;
    for (int u = tid; u < NQ / 4; u += 256) {
        float4 v = srow[u];
        v.x = __expf(v.x - bm); v.y = __expf(v.y - bm);
        v.z = __expf(v.z - bm); v.w = __expf(v.w - bm);
        srow[u] = v;
        sum += v.x + v.y + v.z + v.w;
    }
#pragma unroll
    for (int o = 16; o; o >>= 1) sum += __shfl_xor_sync(0xffffffffu, sum, o);
    if ((tid & 31) == 0) red[tid >> 5] = sum;
    __syncthreads();
    float tot = 0.f;
#pragma unroll
    for (int w = 0; w < 8; w++) tot += red[w];
    float inv = 1.f / tot;

    uint2* dhi = (uint2*)(g_attn_hi + (size_t)row * NQ);
    uint2* dlo = (uint2*)(g_attn_lo + (size_t)row * NQ);
    for (int u = tid; u < NQ / 4; u += 256) {
        float4 v = srow[u];
        float p0 = v.x * inv, p1 = v.y * inv, p2 = v.z * inv, p3 = v.w * inv;
        __nv_bfloat16 h0, l0, h1, l1, h2, l2, h3, l3;
        split_bf16(p0, h0, l0); split_bf16(p1, h1, l1);
        split_bf16(p2, h2, l2); split_bf16(p3, h3, l3);
        __nv_bfloat162 hp0 = {h0, h1}, hp1 = {h2, h3};
        __nv_bfloat162 lp0 = {l0, l1}, lp1 = {l2, l3};
        uint2 oh, ol;
        oh.x = *(unsigned*)&hp0; oh.y = *(unsigned*)&hp1;
        ol.x = *(unsigned*)&lp0; ol.y = *(unsigned*)&lp1;
        dhi[u] = oh;
        dlo[u] = ol;
    }
}

// ---------------- K5: zero output (required before atomic split-K epilogue) ----------
__global__ void zero_kernel(float* __restrict__ out) {
    out[(size_t)blockIdx.x * 256 + threadIdx.x] = 0.f;
}

// ---------------- launch ----------------
extern "C" void kernel_launch(void* const* d_in, const int* in_sizes, int n_in,
                              void* d_out, int out_size) {
    const float* mag   = (const float*)d_in[0];
    const float* phase = (const float*)d_in[1];
    const int*   ei    = (const int*)d_in[2];
    const float* rbf   = (const float*)d_in[3];
    const float* W1    = (const float*)d_in[4];
    const float* b1    = (const float*)d_in[5];
    const float* W2    = (const float*)d_in[6];
    const float* b2    = (const float*)d_in[7];
    float*       out   = (float*)d_out;

    const float inv_sqrt_d = 0.08838834764831843f;   // 1/sqrt(128)
    const int smem_bytes = 2 * 4 * TSZ * (int)sizeof(__nv_bfloat16);   // 81920

    cudaFuncSetAttribute(gemm_kernel<0>, cudaFuncAttributeMaxDynamicSharedMemorySize, smem_bytes);
    cudaFuncSetAttribute(gemm_kernel<1>, cudaFuncAttributeMaxDynamicSharedMemorySize, smem_bytes);

    prep_kernel<<<(NQ * DQ) / 256, 256>>>(mag, phase);
    gemm_kernel<0><<<dim3(NQ / 128, NQ / 128), 256, smem_bytes>>>(nullptr, inv_sqrt_d);
    bias_kernel<<<EQ / 256, 256>>>(ei, rbf, W1, b1, W2, b2);
    softmax_kernel<<<NQ, 256>>>();
    zero_kernel<<<(NQ * 256) / 256, 256>>>(out);
    gemm_kernel<1><<<dim3(2, NQ / 128, 4), 256, smem_bytes>>>(out, 1.0f);
}